// round 14
// baseline (speedup 1.0000x reference)
#include <cuda_runtime.h>
#include <math.h>

// ---------------- constants ----------------
#define VOCAB 20000
#define Dd 100
#define Hh 100
#define N_NODE 256
#define Rr 8
#define Ss 52
#define SP 50
#define Ee 20000
#define NREV 2048

typedef unsigned long long u64;

__device__ __forceinline__ void ffma2(u64 &c, u64 a, u64 b) {
    asm("fma.rn.f32x2 %0, %1, %2, %0;" : "+l"(c) : "l"(a), "l"(b));
}
__device__ __forceinline__ float2 f2u(u64 v) {
    float2 r; asm("mov.b64 {%0, %1}, %2;" : "=f"(r.x), "=f"(r.y) : "l"(v)); return r;
}
__device__ __forceinline__ u64 u2f(float2 v) {
    u64 r; asm("mov.b64 %0, {%1, %2};" : "=l"(r) : "f"(v.x), "f"(v.y)); return r;
}

union V4 { float4 f; u64 u[2]; };

// ---------------- device scratch ----------------
__device__ __align__(16) float g_proj[VOCAB * 300];     // [v][k*100+h]
__device__ __align__(16) float4 g_wt4[25 * 300];        // [j][n]
__device__ __align__(16) float4 g_w2t2[50 * 50];        // [h2][c2] 2x2 tile of w2^T
__device__ __align__(16) float g_cmax[2 * NREV * Hh];   // [row][h]
__device__ __align__(16) float g_P[2 * NREV * Dd];      // [row][d]
__device__ __align__(16) float g_Qt[50 * 512 * 2];      // [d2][n] float2
__device__ __align__(16) float g_zw[2 * NREV];
__device__ __align__(16) float g_pc[2 * NREV];
__device__ __align__(16) float g_A[N_NODE * N_NODE * Rr];
__device__ __align__(16) float g_B[N_NODE * N_NODE * Rr];

// ---------------- K0: transpose conv_w -> wt4, fc_w2_w -> w2t2 (2x2 tiles) ----------------
__global__ void transpose_kernel(const float* __restrict__ convw, const float* __restrict__ w2)
{
    const int t = blockIdx.x * 256 + threadIdx.x;
    if (t < 7500) {
        const int j = t / 300, n = t - j * 300;
        const int h = n % 100, k = n / 100;
        const float* s = convw + h * 300 + k * 100 + 4 * j;
        g_wt4[t] = make_float4(s[0], s[1], s[2], s[3]);
    } else if (t < 10000) {
        const int i = t - 7500;              // i = h2*50 + c2
        const int h2 = i / 50, c2 = i - h2 * 50;
        g_w2t2[i] = make_float4(w2[(2 * c2) * 100 + 2 * h2],
                                w2[(2 * c2 + 1) * 100 + 2 * h2],
                                w2[(2 * c2) * 100 + 2 * h2 + 1],
                                w2[(2 * c2 + 1) * 100 + 2 * h2 + 1]);
    }
}

// ---------------- K1: proj via f32x2, 16 vocab rows / block, 1 column/thread ----------
#define TVP 16
__global__ void __launch_bounds__(320) proj_kernel(const float* __restrict__ emb)
{
    __shared__ __align__(16) float4 esh[TVP][25];       // 6.4KB
    const int v0 = blockIdx.x * TVP;
    const int tid = threadIdx.x;

    for (int i = tid; i < TVP * 25; i += 320) {
        int v = i / 25, d4 = i % 25;
        esh[v][d4] = reinterpret_cast<const float4*>(emb)[(v0 + v) * 25 + d4];
    }
    __syncthreads();
    if (tid >= 300) return;

    const int n = tid;

    u64 acc[TVP];
#pragma unroll
    for (int v = 0; v < TVP; v++) acc[v] = 0ull;

#pragma unroll 5
    for (int j = 0; j < 25; j++) {
        V4 w; w.f = __ldg(reinterpret_cast<const float4*>(g_wt4) + j * 300 + n);  // coalesced
#pragma unroll
        for (int v = 0; v < TVP; v++) {
            V4 e; e.f = esh[v][j];
            ffma2(acc[v], e.u[0], w.u[0]);
            ffma2(acc[v], e.u[1], w.u[1]);
        }
    }
#pragma unroll
    for (int v = 0; v < TVP; v++) {
        float2 a = f2u(acc[v]);
        g_proj[(v0 + v) * 300 + n] = a.x + a.y;
    }
}

// ---------------- K2: per-review: conv + z + cmax + zw (R11 version) ----------------
__global__ void review_kernel(const int* __restrict__ ur, const int* __restrict__ ir,
                              const float* __restrict__ convb,
                              const float* __restrict__ fcw, const float* __restrict__ fcb,
                              const float* __restrict__ hrw,
                              float* __restrict__ out)
{
    __shared__ __align__(16) float c_sh[SP * 104];
    __shared__ __align__(16) float cb[Hh], fw[Hh];
    __shared__ float zsh[SP];
    __shared__ int tok[Ss];

    const int bid = blockIdx.x;
    const int br  = bid >> 11;
    const int idx = bid & 2047;
    const int tid = threadIdx.x;
    const int* revs = br ? ir : ur;

    if (tid < Ss)  tok[tid] = revs[idx * Ss + tid];
    if (tid >= 64 && tid < 64 + Hh) { int h = tid - 64; cb[h] = convb[h]; fw[h] = fcw[h]; }
    __syncthreads();

    for (int i = tid; i < SP * 25; i += 256) {
        const int s = i / 25, h4 = i - s * 25;
        const float4 a = __ldg(reinterpret_cast<const float4*>(g_proj + tok[s]     * 300      ) + h4);
        const float4 b = __ldg(reinterpret_cast<const float4*>(g_proj + tok[s + 1] * 300 + 100) + h4);
        const float4 c = __ldg(reinterpret_cast<const float4*>(g_proj + tok[s + 2] * 300 + 200) + h4);
        const float4 bb = reinterpret_cast<const float4*>(cb)[h4];
        float4 v;
        v.x = fmaxf(bb.x + a.x + b.x + c.x, 0.f);
        v.y = fmaxf(bb.y + a.y + b.y + c.y, 0.f);
        v.z = fmaxf(bb.z + a.z + b.z + c.z, 0.f);
        v.w = fmaxf(bb.w + a.w + b.w + c.w, 0.f);
        reinterpret_cast<float4*>(c_sh + s * 104)[h4] = v;
    }
    __syncthreads();

    // rho -> z on warps 0-1
    if (tid < SP) {
        const float4* crow = reinterpret_cast<const float4*>(c_sh + tid * 104);
        float x = fcb[0];
#pragma unroll 5
        for (int j = 0; j < 25; j++) {
            float4 v = crow[j];
            float4 w = reinterpret_cast<const float4*>(fw)[j];
            x += v.x * w.x + v.y * w.y + v.z * w.z + v.w * w.w;
        }
        float rho = 1.f / (1.f + expf(-x));
        float z = rintf(rho);
        zsh[tid] = z;
        out[2 * Ee + bid * SP + tid] = z;
    }
    // cmax on warps 2-5 -> straight to global
    if (tid >= 64 && tid < 64 + Hh) {
        const int h = tid - 64;
        float m = 0.f;
#pragma unroll 5
        for (int s = 0; s < SP; s++) m = fmaxf(m, c_sh[s * 104 + h]);
        g_cmax[bid * Hh + h] = m;
    }
    __syncthreads();

    // zw reduction on warp 6
    if (tid >= 192 && tid < 224) {
        const int l = tid - 192;
        float a = (l < SP) ? zsh[l] * hrw[br * SP + l] : 0.f;
        if (l + 32 < SP) a += zsh[l + 32] * hrw[br * SP + l + 32];
#pragma unroll
        for (int o = 16; o > 0; o >>= 1) a += __shfl_xor_sync(0xffffffffu, a, o);
        if (l == 0) g_zw[bid] = a;
    }
}

// ---------------- K3: P GEMM (exact R11): 2x2-packed, 2 nodes/block, 800 thr, grid 256 --
__global__ void __launch_bounds__(800) pgemm_kernel(const float* __restrict__ w2b,
                                                    const float* __restrict__ hcw)
{
    __shared__ __align__(16) float cms4[16 * 50 * 4];   // [rl][h2] {e,e,o,o} 12.8KB
    __shared__ __align__(8)  float2 ps2[16 * 50];       // results, 6.4KB

    const int tid  = threadIdx.x;
    const int base = blockIdx.x * 16;                   // 2 nodes

    for (int i = tid; i < 16 * Hh; i += 800) {
        const float v = g_cmax[base * Hh + i];
        const int row = i / Hh, h = i - row * Hh;
        *reinterpret_cast<float2*>(cms4 + row * 200 + (h >> 1) * 4 + (h & 1) * 2)
            = make_float2(v, v);
    }
    __syncthreads();

    const int c2 = tid % 50, rl = tid / 50;

    u64 accA = u2f(*reinterpret_cast<const float2*>(w2b + 2 * c2));   // bias + even-h chain
    u64 accB = 0ull;                                                  // odd-h chain
    const float4* cmrow = reinterpret_cast<const float4*>(cms4 + rl * 200);

#pragma unroll 10
    for (int h2 = 0; h2 < 50; h2++) {
        V4 w; w.f = __ldg(reinterpret_cast<const float4*>(g_w2t2) + h2 * 50 + c2); // LDG.128
        V4 cm; cm.f = cmrow[h2];                                                    // LDS.128
        ffma2(accA, cm.u[0], w.u[0]);
        ffma2(accB, cm.u[1], w.u[1]);
    }

    const float2 ra = f2u(accA), rb = f2u(accB);
    const float2 res = make_float2(ra.x + rb.x, ra.y + rb.y);
    reinterpret_cast<float2*>(g_P + (base + rl) * Dd)[c2] = res;
    ps2[rl * 50 + c2] = res;
    __syncthreads();

    // Qt epilogue: q = sum_r (r ascending) per node
    if (tid < 100) {
        const int nl = tid / 50, cc = tid % 50;
        float2 q = make_float2(0.f, 0.f);
#pragma unroll
        for (int r = 0; r < Rr; r++) {
            const float2 p = ps2[(nl * Rr + r) * 50 + cc];
            q.x += p.x; q.y += p.y;
        }
        const int n = blockIdx.x * 2 + nl;
        *reinterpret_cast<float2*>(g_Qt + cc * 1024 + n * 2) = q;
    }
    // pc epilogue: warps 9-24 handle the 16 rows (800 thr = 25 warps)
    const int wid = tid >> 5, lane = tid & 31;
    if (wid >= 9) {
        const int row = wid - 9;                        // 0..15
        const int br = (base + row) >> 11;
        const float* pr = reinterpret_cast<const float*>(ps2) + row * 100;
        float a = 0.f;
#pragma unroll
        for (int j = 0; j < 4; j++) {
            int d = lane + 32 * j;
            if (d < Dd) a += pr[d] * __ldg(hcw + br * Dd + d);
        }
#pragma unroll
        for (int o = 16; o > 0; o >>= 1) a += __shfl_xor_sync(0xffffffffu, a, o);
        if (lane == 0) g_pc[base + row] = a;
    }
}

// ---------------- K4: pair scores — single node/block, pipelined q + LDS.128 ----------
__global__ void __launch_bounds__(256) pair_kernel()
{
    __shared__ __align__(16) float Pt[50 * 16];

    const int pb  = blockIdx.y;
    const int a   = blockIdx.x;
    const int tid = threadIdx.x;

    const float* Pbase = g_P + (pb * NREV + a * Rr) * Dd;
    for (int i = tid; i < Rr * Dd; i += 256) {
        int r = i / Dd, d = i - r * Dd;
        Pt[(d >> 1) * 16 + r * 2 + (d & 1)] = Pbase[i];
    }
    __syncthreads();

    const int off = (1 - pb) * N_NODE;
    const u64* qcol = reinterpret_cast<const u64*>(g_Qt) + off + tid;

    u64 acc[Rr];
#pragma unroll
    for (int r = 0; r < Rr; r++) acc[r] = 0ull;

    u64 q[2][5];
#pragma unroll
    for (int t = 0; t < 5; t++) q[0][t] = __ldg(qcol + t * 512);

#pragma unroll
    for (int c = 0; c < 10; c++) {
        const int cur = c & 1, nxt = cur ^ 1;
        if (c < 9) {
#pragma unroll
            for (int t = 0; t < 5; t++) q[nxt][t] = __ldg(qcol + ((c + 1) * 5 + t) * 512);
        }
#pragma unroll
        for (int t = 0; t < 5; t++) {
            const int d2 = c * 5 + t;
            const float4* row = reinterpret_cast<const float4*>(Pt + d2 * 16);
            V4 p0, p1, p2, p3;
            p0.f = row[0]; p1.f = row[1]; p2.f = row[2]; p3.f = row[3];
            u64 qq = q[cur][t];
            ffma2(acc[0], qq, p0.u[0]);
            ffma2(acc[1], qq, p0.u[1]);
            ffma2(acc[2], qq, p1.u[0]);
            ffma2(acc[3], qq, p1.u[1]);
            ffma2(acc[4], qq, p2.u[0]);
            ffma2(acc[5], qq, p2.u[1]);
            ffma2(acc[6], qq, p3.u[0]);
            ffma2(acc[7], qq, p3.u[1]);
        }
    }

    float v[Rr];
#pragma unroll
    for (int r = 0; r < Rr; r++) { float2 t = f2u(acc[r]); v[r] = t.x + t.y; }
    float* dst = (pb ? g_B : g_A) + (a * N_NODE + tid) * Rr;
    reinterpret_cast<float4*>(dst)[0] = make_float4(v[0], v[1], v[2], v[3]);
    reinterpret_cast<float4*>(dst)[1] = make_float4(v[4], v[5], v[6], v[7]);
}

// ---------------- K5: per-edge predictions ----------------
__global__ void edge_kernel(const int* __restrict__ uid, const int* __restrict__ iid,
                            const float* __restrict__ ubias, const float* __restrict__ ibias,
                            const float* __restrict__ gbias, float* __restrict__ out)
{
    const int e = blockIdx.x * 256 + threadIdx.x;
    if (e >= Ee) return;
    const int u = uid[e], i = iid[e];

    const float4* A4 = reinterpret_cast<const float4*>(g_A + (u * N_NODE + i) * Rr);
    const float4* B4 = reinterpret_cast<const float4*>(g_B + (i * N_NODE + u) * Rr);
    float Av[Rr], Bv[Rr];
    *reinterpret_cast<float4*>(Av)     = A4[0];
    *reinterpret_cast<float4*>(Av + 4) = A4[1];
    *reinterpret_cast<float4*>(Bv)     = B4[0];
    *reinterpret_cast<float4*>(Bv + 4) = B4[1];

    const float* zwu = g_zw + u * Rr;
    const float* zwi = g_zw + NREV + i * Rr;
    const float* pcu = g_pc + u * Rr;
    const float* pci = g_pc + NREV + i * Rr;

    float pr = ubias[u] + ibias[i] + gbias[0];
    float pc = 0.f;
#pragma unroll
    for (int r = 0; r < Rr; r++) {
        float su = 1.f / (1.f + expf(-Av[r]));
        float sv = 1.f / (1.f + expf(-Bv[r]));
        pr += su * zwu[r] + sv * zwi[r];
        pc += su * pcu[r] + sv * pci[r];
    }
    out[e]      = pr;
    out[Ee + e] = pc;
}

// ---------------- launcher ----------------
extern "C" void kernel_launch(void* const* d_in, const int* in_sizes, int n_in,
                              void* d_out, int out_size)
{
    const int*   user_reviews = (const int*)  d_in[0];
    const int*   item_reviews = (const int*)  d_in[1];
    const int*   uid          = (const int*)  d_in[2];
    const int*   iid          = (const int*)  d_in[3];
    const float* emb_table    = (const float*)d_in[4];
    const float* conv_w       = (const float*)d_in[5];
    const float* conv_b       = (const float*)d_in[6];
    const float* fc_w_w       = (const float*)d_in[7];
    const float* fc_w_b       = (const float*)d_in[8];
    const float* fc_w2_w      = (const float*)d_in[9];
    const float* fc_w2_b      = (const float*)d_in[10];
    const float* h_r_w        = (const float*)d_in[11];
    const float* h_c_w        = (const float*)d_in[12];
    const float* user_bias    = (const float*)d_in[13];
    const float* item_bias    = (const float*)d_in[14];
    const float* global_bias  = (const float*)d_in[15];
    float* out = (float*)d_out;

    transpose_kernel<<<40, 256>>>(conv_w, fc_w2_w);
    proj_kernel<<<VOCAB / TVP, 320>>>(emb_table);
    review_kernel<<<2 * NREV, 256>>>(user_reviews, item_reviews,
                                     conv_b, fc_w_w, fc_w_b, h_r_w, out);
    pgemm_kernel<<<256, 800>>>(fc_w2_b, h_c_w);
    pair_kernel<<<dim3(N_NODE, 2), 256>>>();
    edge_kernel<<<(Ee + 255) / 256, 256>>>(uid, iid, user_bias, item_bias, global_bias, out);
}

// round 15
// speedup vs baseline: 1.1482x; 1.1482x over previous
#include <cuda_runtime.h>
#include <math.h>

// ---------------- constants ----------------
#define VOCAB 20000
#define Dd 100
#define Hh 100
#define N_NODE 256
#define Rr 8
#define Ss 52
#define SP 50
#define Ee 20000
#define NREV 2048

typedef unsigned long long u64;

__device__ __forceinline__ void ffma2(u64 &c, u64 a, u64 b) {
    asm("fma.rn.f32x2 %0, %1, %2, %0;" : "+l"(c) : "l"(a), "l"(b));
}
__device__ __forceinline__ u64 fadd2(u64 a, u64 b) {
    u64 r; asm("add.rn.f32x2 %0, %1, %2;" : "=l"(r) : "l"(a), "l"(b)); return r;
}
__device__ __forceinline__ float2 f2u(u64 v) {
    float2 r; asm("mov.b64 {%0, %1}, %2;" : "=f"(r.x), "=f"(r.y) : "l"(v)); return r;
}
__device__ __forceinline__ u64 u2f(float2 v) {
    u64 r; asm("mov.b64 %0, {%1, %2};" : "=l"(r) : "f"(v.x), "f"(v.y)); return r;
}

union V4 { float4 f; u64 u[2]; };

// ---------------- device scratch ----------------
__device__ __align__(16) float g_proj[VOCAB * 300];     // [v][k*100+h]
__device__ __align__(16) float4 g_wt4[25 * 300];        // [j][n]
__device__ __align__(16) float4 g_w2t2[50 * 50];        // [h2][c2] 2x2 tile of w2^T
__device__ __align__(16) float g_cmax[2 * NREV * Hh];   // [row][h]
__device__ __align__(16) float g_P[2 * NREV * Dd];      // [row][d]
__device__ __align__(16) float g_Qt[50 * 512 * 2];      // [d2][n] float2
__device__ __align__(16) float g_zw[2 * NREV];
__device__ __align__(16) float g_pc[2 * NREV];
__device__ __align__(16) float g_A[N_NODE * N_NODE * Rr];
__device__ __align__(16) float g_B[N_NODE * N_NODE * Rr];

// ---------------- K0: transpose conv_w -> wt4, fc_w2_w -> w2t2 (2x2 tiles) ----------------
__global__ void transpose_kernel(const float* __restrict__ convw, const float* __restrict__ w2)
{
    const int t = blockIdx.x * 256 + threadIdx.x;
    if (t < 7500) {
        const int j = t / 300, n = t - j * 300;
        const int h = n % 100, k = n / 100;
        const float* s = convw + h * 300 + k * 100 + 4 * j;
        g_wt4[t] = make_float4(s[0], s[1], s[2], s[3]);
    } else if (t < 10000) {
        const int i = t - 7500;              // i = h2*50 + c2
        const int h2 = i / 50, c2 = i - h2 * 50;
        g_w2t2[i] = make_float4(w2[(2 * c2) * 100 + 2 * h2],
                                w2[(2 * c2 + 1) * 100 + 2 * h2],
                                w2[(2 * c2) * 100 + 2 * h2 + 1],
                                w2[(2 * c2 + 1) * 100 + 2 * h2 + 1]);
    }
}

// ---------------- K1: proj via f32x2, 8 vocab rows / block (R11 exact) ----------------
#define TVP 8
__global__ void proj_kernel(const float* __restrict__ emb)
{
    __shared__ __align__(16) float4 esh[TVP][25];
    const int v0 = blockIdx.x * TVP;
    const int tid = threadIdx.x;

    for (int i = tid; i < TVP * 25; i += 160) {
        int v = i / 25, d4 = i % 25;
        esh[v][d4] = reinterpret_cast<const float4*>(emb)[(v0 + v) * 25 + d4];
    }
    __syncthreads();
    if (tid >= 150) return;

    const int n0 = tid, n1 = tid + 150;

    u64 acc0[TVP], acc1[TVP];
#pragma unroll
    for (int v = 0; v < TVP; v++) { acc0[v] = 0ull; acc1[v] = 0ull; }

#pragma unroll 5
    for (int j = 0; j < 25; j++) {
        V4 w0, w1;
        w0.f = __ldg(reinterpret_cast<const float4*>(g_wt4) + j * 300 + n0);
        w1.f = __ldg(reinterpret_cast<const float4*>(g_wt4) + j * 300 + n1);
#pragma unroll
        for (int v = 0; v < TVP; v++) {
            V4 e; e.f = esh[v][j];
            ffma2(acc0[v], e.u[0], w0.u[0]);
            ffma2(acc0[v], e.u[1], w0.u[1]);
            ffma2(acc1[v], e.u[0], w1.u[0]);
            ffma2(acc1[v], e.u[1], w1.u[1]);
        }
    }
#pragma unroll
    for (int v = 0; v < TVP; v++) {
        float2 a0 = f2u(acc0[v]), a1 = f2u(acc1[v]);
        g_proj[(v0 + v) * 300 + n0] = a0.x + a0.y;
        g_proj[(v0 + v) * 300 + n1] = a1.x + a1.y;
    }
}

// ---------------- K2: per-review: conv + z + cmax + zw (R11 + f32x2 adds) ----------------
__global__ void review_kernel(const int* __restrict__ ur, const int* __restrict__ ir,
                              const float* __restrict__ convb,
                              const float* __restrict__ fcw, const float* __restrict__ fcb,
                              const float* __restrict__ hrw,
                              float* __restrict__ out)
{
    __shared__ __align__(16) float c_sh[SP * 104];
    __shared__ __align__(16) float cb[Hh], fw[Hh];
    __shared__ float zsh[SP];
    __shared__ int tok[Ss];

    const int bid = blockIdx.x;
    const int br  = bid >> 11;
    const int idx = bid & 2047;
    const int tid = threadIdx.x;
    const int* revs = br ? ir : ur;

    if (tid < Ss)  tok[tid] = revs[idx * Ss + tid];
    if (tid >= 64 && tid < 64 + Hh) { int h = tid - 64; cb[h] = convb[h]; fw[h] = fcw[h]; }
    __syncthreads();

    for (int i = tid; i < SP * 25; i += 256) {
        const int s = i / 25, h4 = i - s * 25;
        V4 a, b, c, bb, v;
        a.f  = __ldg(reinterpret_cast<const float4*>(g_proj + tok[s]     * 300      ) + h4);
        b.f  = __ldg(reinterpret_cast<const float4*>(g_proj + tok[s + 1] * 300 + 100) + h4);
        c.f  = __ldg(reinterpret_cast<const float4*>(g_proj + tok[s + 2] * 300 + 200) + h4);
        bb.f = reinterpret_cast<const float4*>(cb)[h4];
        // same order as scalar version: ((bb + a) + b) + c  -> bitwise identical
        const u64 s0 = fadd2(fadd2(fadd2(bb.u[0], a.u[0]), b.u[0]), c.u[0]);
        const u64 s1 = fadd2(fadd2(fadd2(bb.u[1], a.u[1]), b.u[1]), c.u[1]);
        const float2 f0 = f2u(s0), f1 = f2u(s1);
        v.f = make_float4(fmaxf(f0.x, 0.f), fmaxf(f0.y, 0.f),
                          fmaxf(f1.x, 0.f), fmaxf(f1.y, 0.f));
        reinterpret_cast<float4*>(c_sh + s * 104)[h4] = v.f;
    }
    __syncthreads();

    // rho -> z on warps 0-1 (untouched: z must stay bitwise)
    if (tid < SP) {
        const float4* crow = reinterpret_cast<const float4*>(c_sh + tid * 104);
        float x = fcb[0];
#pragma unroll 5
        for (int j = 0; j < 25; j++) {
            float4 v = crow[j];
            float4 w = reinterpret_cast<const float4*>(fw)[j];
            x += v.x * w.x + v.y * w.y + v.z * w.z + v.w * w.w;
        }
        float rho = 1.f / (1.f + expf(-x));
        float z = rintf(rho);
        zsh[tid] = z;
        out[2 * Ee + bid * SP + tid] = z;
    }
    // cmax on warps 2-5 -> straight to global
    if (tid >= 64 && tid < 64 + Hh) {
        const int h = tid - 64;
        float m = 0.f;
#pragma unroll 5
        for (int s = 0; s < SP; s++) m = fmaxf(m, c_sh[s * 104 + h]);
        g_cmax[bid * Hh + h] = m;
    }
    __syncthreads();

    // zw reduction on warp 6
    if (tid >= 192 && tid < 224) {
        const int l = tid - 192;
        float a = (l < SP) ? zsh[l] * hrw[br * SP + l] : 0.f;
        if (l + 32 < SP) a += zsh[l + 32] * hrw[br * SP + l + 32];
#pragma unroll
        for (int o = 16; o > 0; o >>= 1) a += __shfl_xor_sync(0xffffffffu, a, o);
        if (l == 0) g_zw[bid] = a;
    }
}

// ---------------- K3: P GEMM (R11 exact): 2x2-packed, 2 nodes/block, 800 thr, grid 256 --
__global__ void __launch_bounds__(800) pgemm_kernel(const float* __restrict__ w2b,
                                                    const float* __restrict__ hcw)
{
    __shared__ __align__(16) float cms4[16 * 50 * 4];   // [rl][h2] {e,e,o,o} 12.8KB
    __shared__ __align__(8)  float2 ps2[16 * 50];       // results, 6.4KB

    const int tid  = threadIdx.x;
    const int base = blockIdx.x * 16;                   // 2 nodes

    for (int i = tid; i < 16 * Hh; i += 800) {
        const float v = g_cmax[base * Hh + i];
        const int row = i / Hh, h = i - row * Hh;
        *reinterpret_cast<float2*>(cms4 + row * 200 + (h >> 1) * 4 + (h & 1) * 2)
            = make_float2(v, v);
    }
    __syncthreads();

    const int c2 = tid % 50, rl = tid / 50;

    u64 accA = u2f(*reinterpret_cast<const float2*>(w2b + 2 * c2));   // bias + even-h chain
    u64 accB = 0ull;                                                  // odd-h chain
    const float4* cmrow = reinterpret_cast<const float4*>(cms4 + rl * 200);

#pragma unroll 10
    for (int h2 = 0; h2 < 50; h2++) {
        V4 w; w.f = __ldg(reinterpret_cast<const float4*>(g_w2t2) + h2 * 50 + c2); // LDG.128
        V4 cm; cm.f = cmrow[h2];                                                    // LDS.128
        ffma2(accA, cm.u[0], w.u[0]);
        ffma2(accB, cm.u[1], w.u[1]);
    }

    const float2 ra = f2u(accA), rb = f2u(accB);
    const float2 res = make_float2(ra.x + rb.x, ra.y + rb.y);
    reinterpret_cast<float2*>(g_P + (base + rl) * Dd)[c2] = res;
    ps2[rl * 50 + c2] = res;
    __syncthreads();

    // Qt epilogue: q = sum_r (r ascending) per node
    if (tid < 100) {
        const int nl = tid / 50, cc = tid % 50;
        float2 q = make_float2(0.f, 0.f);
#pragma unroll
        for (int r = 0; r < Rr; r++) {
            const float2 p = ps2[(nl * Rr + r) * 50 + cc];
            q.x += p.x; q.y += p.y;
        }
        const int n = blockIdx.x * 2 + nl;
        *reinterpret_cast<float2*>(g_Qt + cc * 1024 + n * 2) = q;
    }
    // pc epilogue: warps 9-24 handle the 16 rows (800 thr = 25 warps)
    const int wid = tid >> 5, lane = tid & 31;
    if (wid >= 9) {
        const int row = wid - 9;                        // 0..15
        const int br = (base + row) >> 11;
        const float* pr = reinterpret_cast<const float*>(ps2) + row * 100;
        float a = 0.f;
#pragma unroll
        for (int j = 0; j < 4; j++) {
            int d = lane + 32 * j;
            if (d < Dd) a += pr[d] * __ldg(hcw + br * Dd + d);
        }
#pragma unroll
        for (int o = 16; o > 0; o >>= 1) a += __shfl_xor_sync(0xffffffffu, a, o);
        if (lane == 0) g_pc[base + row] = a;
    }
}

// ---------------- K4: pair scores — single node/block, pipelined q + LDS.128 ----------
__global__ void __launch_bounds__(256) pair_kernel()
{
    __shared__ __align__(16) float Pt[50 * 16];

    const int pb  = blockIdx.y;
    const int a   = blockIdx.x;
    const int tid = threadIdx.x;

    const float* Pbase = g_P + (pb * NREV + a * Rr) * Dd;
    for (int i = tid; i < Rr * Dd; i += 256) {
        int r = i / Dd, d = i - r * Dd;
        Pt[(d >> 1) * 16 + r * 2 + (d & 1)] = Pbase[i];
    }
    __syncthreads();

    const int off = (1 - pb) * N_NODE;
    const u64* qcol = reinterpret_cast<const u64*>(g_Qt) + off + tid;

    u64 acc[Rr];
#pragma unroll
    for (int r = 0; r < Rr; r++) acc[r] = 0ull;

    u64 q[2][5];
#pragma unroll
    for (int t = 0; t < 5; t++) q[0][t] = __ldg(qcol + t * 512);

#pragma unroll
    for (int c = 0; c < 10; c++) {
        const int cur = c & 1, nxt = cur ^ 1;
        if (c < 9) {
#pragma unroll
            for (int t = 0; t < 5; t++) q[nxt][t] = __ldg(qcol + ((c + 1) * 5 + t) * 512);
        }
#pragma unroll
        for (int t = 0; t < 5; t++) {
            const int d2 = c * 5 + t;
            const float4* row = reinterpret_cast<const float4*>(Pt + d2 * 16);
            V4 p0, p1, p2, p3;
            p0.f = row[0]; p1.f = row[1]; p2.f = row[2]; p3.f = row[3];
            u64 qq = q[cur][t];
            ffma2(acc[0], qq, p0.u[0]);
            ffma2(acc[1], qq, p0.u[1]);
            ffma2(acc[2], qq, p1.u[0]);
            ffma2(acc[3], qq, p1.u[1]);
            ffma2(acc[4], qq, p2.u[0]);
            ffma2(acc[5], qq, p2.u[1]);
            ffma2(acc[6], qq, p3.u[0]);
            ffma2(acc[7], qq, p3.u[1]);
        }
    }

    float v[Rr];
#pragma unroll
    for (int r = 0; r < Rr; r++) { float2 t = f2u(acc[r]); v[r] = t.x + t.y; }
    float* dst = (pb ? g_B : g_A) + (a * N_NODE + tid) * Rr;
    reinterpret_cast<float4*>(dst)[0] = make_float4(v[0], v[1], v[2], v[3]);
    reinterpret_cast<float4*>(dst)[1] = make_float4(v[4], v[5], v[6], v[7]);
}

// ---------------- K5: per-edge predictions ----------------
__global__ void edge_kernel(const int* __restrict__ uid, const int* __restrict__ iid,
                            const float* __restrict__ ubias, const float* __restrict__ ibias,
                            const float* __restrict__ gbias, float* __restrict__ out)
{
    const int e = blockIdx.x * 256 + threadIdx.x;
    if (e >= Ee) return;
    const int u = uid[e], i = iid[e];

    const float4* A4 = reinterpret_cast<const float4*>(g_A + (u * N_NODE + i) * Rr);
    const float4* B4 = reinterpret_cast<const float4*>(g_B + (i * N_NODE + u) * Rr);
    float Av[Rr], Bv[Rr];
    *reinterpret_cast<float4*>(Av)     = A4[0];
    *reinterpret_cast<float4*>(Av + 4) = A4[1];
    *reinterpret_cast<float4*>(Bv)     = B4[0];
    *reinterpret_cast<float4*>(Bv + 4) = B4[1];

    const float* zwu = g_zw + u * Rr;
    const float* zwi = g_zw + NREV + i * Rr;
    const float* pcu = g_pc + u * Rr;
    const float* pci = g_pc + NREV + i * Rr;

    float pr = ubias[u] + ibias[i] + gbias[0];
    float pc = 0.f;
#pragma unroll
    for (int r = 0; r < Rr; r++) {
        float su = 1.f / (1.f + expf(-Av[r]));
        float sv = 1.f / (1.f + expf(-Bv[r]));
        pr += su * zwu[r] + sv * zwi[r];
        pc += su * pcu[r] + sv * pci[r];
    }
    out[e]      = pr;
    out[Ee + e] = pc;
}

// ---------------- launcher ----------------
extern "C" void kernel_launch(void* const* d_in, const int* in_sizes, int n_in,
                              void* d_out, int out_size)
{
    const int*   user_reviews = (const int*)  d_in[0];
    const int*   item_reviews = (const int*)  d_in[1];
    const int*   uid          = (const int*)  d_in[2];
    const int*   iid          = (const int*)  d_in[3];
    const float* emb_table    = (const float*)d_in[4];
    const float* conv_w       = (const float*)d_in[5];
    const float* conv_b       = (const float*)d_in[6];
    const float* fc_w_w       = (const float*)d_in[7];
    const float* fc_w_b       = (const float*)d_in[8];
    const float* fc_w2_w      = (const float*)d_in[9];
    const float* fc_w2_b      = (const float*)d_in[10];
    const float* h_r_w        = (const float*)d_in[11];
    const float* h_c_w        = (const float*)d_in[12];
    const float* user_bias    = (const float*)d_in[13];
    const float* item_bias    = (const float*)d_in[14];
    const float* global_bias  = (const float*)d_in[15];
    float* out = (float*)d_out;

    transpose_kernel<<<40, 256>>>(conv_w, fc_w2_w);
    proj_kernel<<<VOCAB / TVP, 160>>>(emb_table);
    review_kernel<<<2 * NREV, 256>>>(user_reviews, item_reviews,
                                     conv_b, fc_w_w, fc_w_b, h_r_w, out);
    pgemm_kernel<<<256, 800>>>(fc_w2_b, h_c_w);
    pair_kernel<<<dim3(N_NODE, 2), 256>>>();
    edge_kernel<<<(Ee + 255) / 256, 256>>>(uid, iid, user_bias, item_bias, global_bias, out);
}

// round 16
// speedup vs baseline: 1.1689x; 1.0180x over previous
#include <cuda_runtime.h>
#include <math.h>

// ---------------- constants ----------------
#define VOCAB 20000
#define Dd 100
#define Hh 100
#define N_NODE 256
#define Rr 8
#define Ss 52
#define SP 50
#define Ee 20000
#define NREV 2048

typedef unsigned long long u64;

__device__ __forceinline__ void ffma2(u64 &c, u64 a, u64 b) {
    asm("fma.rn.f32x2 %0, %1, %2, %0;" : "+l"(c) : "l"(a), "l"(b));
}
__device__ __forceinline__ u64 fadd2(u64 a, u64 b) {
    u64 r; asm("add.rn.f32x2 %0, %1, %2;" : "=l"(r) : "l"(a), "l"(b)); return r;
}
__device__ __forceinline__ float2 f2u(u64 v) {
    float2 r; asm("mov.b64 {%0, %1}, %2;" : "=f"(r.x), "=f"(r.y) : "l"(v)); return r;
}
__device__ __forceinline__ u64 u2f(float2 v) {
    u64 r; asm("mov.b64 %0, {%1, %2};" : "=l"(r) : "f"(v.x), "f"(v.y)); return r;
}

union V4 { float4 f; u64 u[2]; };

// ---------------- device scratch ----------------
__device__ __align__(16) float g_proj[VOCAB * 300];     // [v][k*100+h]
__device__ __align__(16) float4 g_wt4[25 * 300];        // [j][n]
__device__ __align__(16) float4 g_w2t2[50 * 50];        // [h2][c2] 2x2 tile of w2^T
__device__ __align__(16) float g_cmax[2 * NREV * Hh];   // [row][h]
__device__ __align__(16) float g_P[2 * NREV * Dd];      // [row][d]
__device__ __align__(16) float g_Qt[50 * 512 * 2];      // [d2][n] float2
__device__ __align__(16) float g_zw[2 * NREV];
__device__ __align__(16) float g_pc[2 * NREV];
__device__ __align__(16) float g_A[N_NODE * N_NODE * Rr];
__device__ __align__(16) float g_B[N_NODE * N_NODE * Rr];

// ---------------- K0: transpose conv_w -> wt4, fc_w2_w -> w2t2 (2x2 tiles) ----------------
__global__ void transpose_kernel(const float* __restrict__ convw, const float* __restrict__ w2)
{
    const int t = blockIdx.x * 256 + threadIdx.x;
    if (t < 7500) {
        const int j = t / 300, n = t - j * 300;
        const int h = n % 100, k = n / 100;
        const float* s = convw + h * 300 + k * 100 + 4 * j;
        g_wt4[t] = make_float4(s[0], s[1], s[2], s[3]);
    } else if (t < 10000) {
        const int i = t - 7500;              // i = h2*50 + c2
        const int h2 = i / 50, c2 = i - h2 * 50;
        g_w2t2[i] = make_float4(w2[(2 * c2) * 100 + 2 * h2],
                                w2[(2 * c2 + 1) * 100 + 2 * h2],
                                w2[(2 * c2) * 100 + 2 * h2 + 1],
                                w2[(2 * c2 + 1) * 100 + 2 * h2 + 1]);
    }
}

// ---------------- K1: proj via f32x2, 8 vocab rows / block (R11 exact) ----------------
#define TVP 8
__global__ void proj_kernel(const float* __restrict__ emb)
{
    __shared__ __align__(16) float4 esh[TVP][25];
    const int v0 = blockIdx.x * TVP;
    const int tid = threadIdx.x;

    for (int i = tid; i < TVP * 25; i += 160) {
        int v = i / 25, d4 = i % 25;
        esh[v][d4] = reinterpret_cast<const float4*>(emb)[(v0 + v) * 25 + d4];
    }
    __syncthreads();
    if (tid >= 150) return;

    const int n0 = tid, n1 = tid + 150;

    u64 acc0[TVP], acc1[TVP];
#pragma unroll
    for (int v = 0; v < TVP; v++) { acc0[v] = 0ull; acc1[v] = 0ull; }

#pragma unroll 5
    for (int j = 0; j < 25; j++) {
        V4 w0, w1;
        w0.f = __ldg(reinterpret_cast<const float4*>(g_wt4) + j * 300 + n0);
        w1.f = __ldg(reinterpret_cast<const float4*>(g_wt4) + j * 300 + n1);
#pragma unroll
        for (int v = 0; v < TVP; v++) {
            V4 e; e.f = esh[v][j];
            ffma2(acc0[v], e.u[0], w0.u[0]);
            ffma2(acc0[v], e.u[1], w0.u[1]);
            ffma2(acc1[v], e.u[0], w1.u[0]);
            ffma2(acc1[v], e.u[1], w1.u[1]);
        }
    }
#pragma unroll
    for (int v = 0; v < TVP; v++) {
        float2 a0 = f2u(acc0[v]), a1 = f2u(acc1[v]);
        g_proj[(v0 + v) * 300 + n0] = a0.x + a0.y;
        g_proj[(v0 + v) * 300 + n1] = a1.x + a1.y;
    }
}

// ---------------- K2: per-review: conv (batched gather) + z + cmax + zw ----------------
__global__ void review_kernel(const int* __restrict__ ur, const int* __restrict__ ir,
                              const float* __restrict__ convb,
                              const float* __restrict__ fcw, const float* __restrict__ fcb,
                              const float* __restrict__ hrw,
                              float* __restrict__ out)
{
    __shared__ __align__(16) float c_sh[SP * 104];
    __shared__ __align__(16) float cb[Hh], fw[Hh];
    __shared__ float zsh[SP];
    __shared__ int tok[Ss];

    const int bid = blockIdx.x;
    const int br  = bid >> 11;
    const int idx = bid & 2047;
    const int tid = threadIdx.x;
    const int* revs = br ? ir : ur;

    if (tid < Ss)  tok[tid] = revs[idx * Ss + tid];
    if (tid >= 64 && tid < 64 + Hh) { int h = tid - 64; cb[h] = convb[h]; fw[h] = fcw[h]; }
    __syncthreads();

    // conv: 250 threads x exactly 5 items, all 15 loads front-batched (MLP ~15)
    if (tid < 250) {
        int s[5], h4[5];
        const float4 *pa[5], *pb[5], *pc[5];
#pragma unroll
        for (int j = 0; j < 5; j++) {
            const int item = tid + j * 250;
            s[j] = item / 25; h4[j] = item - s[j] * 25;
            pa[j] = reinterpret_cast<const float4*>(g_proj + tok[s[j]]     * 300      ) + h4[j];
            pb[j] = reinterpret_cast<const float4*>(g_proj + tok[s[j] + 1] * 300 + 100) + h4[j];
            pc[j] = reinterpret_cast<const float4*>(g_proj + tok[s[j] + 2] * 300 + 200) + h4[j];
        }
        V4 a[5], b[5], c[5];
#pragma unroll
        for (int j = 0; j < 5; j++) { a[j].f = __ldg(pa[j]); b[j].f = __ldg(pb[j]); c[j].f = __ldg(pc[j]); }
#pragma unroll
        for (int j = 0; j < 5; j++) {
            V4 bb; bb.f = reinterpret_cast<const float4*>(cb)[h4[j]];
            // same order as scalar: ((bb + a) + b) + c  -> bitwise identical
            const u64 s0 = fadd2(fadd2(fadd2(bb.u[0], a[j].u[0]), b[j].u[0]), c[j].u[0]);
            const u64 s1 = fadd2(fadd2(fadd2(bb.u[1], a[j].u[1]), b[j].u[1]), c[j].u[1]);
            const float2 f0 = f2u(s0), f1 = f2u(s1);
            reinterpret_cast<float4*>(c_sh + s[j] * 104)[h4[j]] =
                make_float4(fmaxf(f0.x, 0.f), fmaxf(f0.y, 0.f),
                            fmaxf(f1.x, 0.f), fmaxf(f1.y, 0.f));
        }
    }
    __syncthreads();

    // rho -> z on warps 0-1 (untouched: z must stay bitwise)
    if (tid < SP) {
        const float4* crow = reinterpret_cast<const float4*>(c_sh + tid * 104);
        float x = fcb[0];
#pragma unroll 5
        for (int j = 0; j < 25; j++) {
            float4 v = crow[j];
            float4 w = reinterpret_cast<const float4*>(fw)[j];
            x += v.x * w.x + v.y * w.y + v.z * w.z + v.w * w.w;
        }
        float rho = 1.f / (1.f + expf(-x));
        float z = rintf(rho);
        zsh[tid] = z;
        out[2 * Ee + bid * SP + tid] = z;
    }
    // cmax on warps 2-5 -> straight to global
    if (tid >= 64 && tid < 64 + Hh) {
        const int h = tid - 64;
        float m = 0.f;
#pragma unroll 5
        for (int s = 0; s < SP; s++) m = fmaxf(m, c_sh[s * 104 + h]);
        g_cmax[bid * Hh + h] = m;
    }
    __syncthreads();

    // zw reduction on warp 6
    if (tid >= 192 && tid < 224) {
        const int l = tid - 192;
        float a = (l < SP) ? zsh[l] * hrw[br * SP + l] : 0.f;
        if (l + 32 < SP) a += zsh[l + 32] * hrw[br * SP + l + 32];
#pragma unroll
        for (int o = 16; o > 0; o >>= 1) a += __shfl_xor_sync(0xffffffffu, a, o);
        if (l == 0) g_zw[bid] = a;
    }
}

// ---------------- K3: P GEMM (R11 exact): 2x2-packed, 2 nodes/block, 800 thr, grid 256 --
__global__ void __launch_bounds__(800) pgemm_kernel(const float* __restrict__ w2b,
                                                    const float* __restrict__ hcw)
{
    __shared__ __align__(16) float cms4[16 * 50 * 4];   // [rl][h2] {e,e,o,o} 12.8KB
    __shared__ __align__(8)  float2 ps2[16 * 50];       // results, 6.4KB

    const int tid  = threadIdx.x;
    const int base = blockIdx.x * 16;                   // 2 nodes

    for (int i = tid; i < 16 * Hh; i += 800) {
        const float v = g_cmax[base * Hh + i];
        const int row = i / Hh, h = i - row * Hh;
        *reinterpret_cast<float2*>(cms4 + row * 200 + (h >> 1) * 4 + (h & 1) * 2)
            = make_float2(v, v);
    }
    __syncthreads();

    const int c2 = tid % 50, rl = tid / 50;

    u64 accA = u2f(*reinterpret_cast<const float2*>(w2b + 2 * c2));   // bias + even-h chain
    u64 accB = 0ull;                                                  // odd-h chain
    const float4* cmrow = reinterpret_cast<const float4*>(cms4 + rl * 200);

#pragma unroll 10
    for (int h2 = 0; h2 < 50; h2++) {
        V4 w; w.f = __ldg(reinterpret_cast<const float4*>(g_w2t2) + h2 * 50 + c2); // LDG.128
        V4 cm; cm.f = cmrow[h2];                                                    // LDS.128
        ffma2(accA, cm.u[0], w.u[0]);
        ffma2(accB, cm.u[1], w.u[1]);
    }

    const float2 ra = f2u(accA), rb = f2u(accB);
    const float2 res = make_float2(ra.x + rb.x, ra.y + rb.y);
    reinterpret_cast<float2*>(g_P + (base + rl) * Dd)[c2] = res;
    ps2[rl * 50 + c2] = res;
    __syncthreads();

    // Qt epilogue: q = sum_r (r ascending) per node
    if (tid < 100) {
        const int nl = tid / 50, cc = tid % 50;
        float2 q = make_float2(0.f, 0.f);
#pragma unroll
        for (int r = 0; r < Rr; r++) {
            const float2 p = ps2[(nl * Rr + r) * 50 + cc];
            q.x += p.x; q.y += p.y;
        }
        const int n = blockIdx.x * 2 + nl;
        *reinterpret_cast<float2*>(g_Qt + cc * 1024 + n * 2) = q;
    }
    // pc epilogue: warps 9-24 handle the 16 rows (800 thr = 25 warps)
    const int wid = tid >> 5, lane = tid & 31;
    if (wid >= 9) {
        const int row = wid - 9;                        // 0..15
        const int br = (base + row) >> 11;
        const float* pr = reinterpret_cast<const float*>(ps2) + row * 100;
        float a = 0.f;
#pragma unroll
        for (int j = 0; j < 4; j++) {
            int d = lane + 32 * j;
            if (d < Dd) a += pr[d] * __ldg(hcw + br * Dd + d);
        }
#pragma unroll
        for (int o = 16; o > 0; o >>= 1) a += __shfl_xor_sync(0xffffffffu, a, o);
        if (lane == 0) g_pc[base + row] = a;
    }
}

// ---------------- K4: pair scores — single node/block, pipelined q + LDS.128 ----------
__global__ void __launch_bounds__(256) pair_kernel()
{
    __shared__ __align__(16) float Pt[50 * 16];

    const int pb  = blockIdx.y;
    const int a   = blockIdx.x;
    const int tid = threadIdx.x;

    const float* Pbase = g_P + (pb * NREV + a * Rr) * Dd;
    for (int i = tid; i < Rr * Dd; i += 256) {
        int r = i / Dd, d = i - r * Dd;
        Pt[(d >> 1) * 16 + r * 2 + (d & 1)] = Pbase[i];
    }
    __syncthreads();

    const int off = (1 - pb) * N_NODE;
    const u64* qcol = reinterpret_cast<const u64*>(g_Qt) + off + tid;

    u64 acc[Rr];
#pragma unroll
    for (int r = 0; r < Rr; r++) acc[r] = 0ull;

    u64 q[2][5];
#pragma unroll
    for (int t = 0; t < 5; t++) q[0][t] = __ldg(qcol + t * 512);

#pragma unroll
    for (int c = 0; c < 10; c++) {
        const int cur = c & 1, nxt = cur ^ 1;
        if (c < 9) {
#pragma unroll
            for (int t = 0; t < 5; t++) q[nxt][t] = __ldg(qcol + ((c + 1) * 5 + t) * 512);
        }
#pragma unroll
        for (int t = 0; t < 5; t++) {
            const int d2 = c * 5 + t;
            const float4* row = reinterpret_cast<const float4*>(Pt + d2 * 16);
            V4 p0, p1, p2, p3;
            p0.f = row[0]; p1.f = row[1]; p2.f = row[2]; p3.f = row[3];
            u64 qq = q[cur][t];
            ffma2(acc[0], qq, p0.u[0]);
            ffma2(acc[1], qq, p0.u[1]);
            ffma2(acc[2], qq, p1.u[0]);
            ffma2(acc[3], qq, p1.u[1]);
            ffma2(acc[4], qq, p2.u[0]);
            ffma2(acc[5], qq, p2.u[1]);
            ffma2(acc[6], qq, p3.u[0]);
            ffma2(acc[7], qq, p3.u[1]);
        }
    }

    float v[Rr];
#pragma unroll
    for (int r = 0; r < Rr; r++) { float2 t = f2u(acc[r]); v[r] = t.x + t.y; }
    float* dst = (pb ? g_B : g_A) + (a * N_NODE + tid) * Rr;
    reinterpret_cast<float4*>(dst)[0] = make_float4(v[0], v[1], v[2], v[3]);
    reinterpret_cast<float4*>(dst)[1] = make_float4(v[4], v[5], v[6], v[7]);
}

// ---------------- K5: per-edge predictions ----------------
__global__ void edge_kernel(const int* __restrict__ uid, const int* __restrict__ iid,
                            const float* __restrict__ ubias, const float* __restrict__ ibias,
                            const float* __restrict__ gbias, float* __restrict__ out)
{
    const int e = blockIdx.x * 256 + threadIdx.x;
    if (e >= Ee) return;
    const int u = uid[e], i = iid[e];

    const float4* A4 = reinterpret_cast<const float4*>(g_A + (u * N_NODE + i) * Rr);
    const float4* B4 = reinterpret_cast<const float4*>(g_B + (i * N_NODE + u) * Rr);
    float Av[Rr], Bv[Rr];
    *reinterpret_cast<float4*>(Av)     = A4[0];
    *reinterpret_cast<float4*>(Av + 4) = A4[1];
    *reinterpret_cast<float4*>(Bv)     = B4[0];
    *reinterpret_cast<float4*>(Bv + 4) = B4[1];

    const float* zwu = g_zw + u * Rr;
    const float* zwi = g_zw + NREV + i * Rr;
    const float* pcu = g_pc + u * Rr;
    const float* pci = g_pc + NREV + i * Rr;

    float pr = ubias[u] + ibias[i] + gbias[0];
    float pc = 0.f;
#pragma unroll
    for (int r = 0; r < Rr; r++) {
        float su = 1.f / (1.f + expf(-Av[r]));
        float sv = 1.f / (1.f + expf(-Bv[r]));
        pr += su * zwu[r] + sv * zwi[r];
        pc += su * pcu[r] + sv * pci[r];
    }
    out[e]      = pr;
    out[Ee + e] = pc;
}

// ---------------- launcher ----------------
extern "C" void kernel_launch(void* const* d_in, const int* in_sizes, int n_in,
                              void* d_out, int out_size)
{
    const int*   user_reviews = (const int*)  d_in[0];
    const int*   item_reviews = (const int*)  d_in[1];
    const int*   uid          = (const int*)  d_in[2];
    const int*   iid          = (const int*)  d_in[3];
    const float* emb_table    = (const float*)d_in[4];
    const float* conv_w       = (const float*)d_in[5];
    const float* conv_b       = (const float*)d_in[6];
    const float* fc_w_w       = (const float*)d_in[7];
    const float* fc_w_b       = (const float*)d_in[8];
    const float* fc_w2_w      = (const float*)d_in[9];
    const float* fc_w2_b      = (const float*)d_in[10];
    const float* h_r_w        = (const float*)d_in[11];
    const float* h_c_w        = (const float*)d_in[12];
    const float* user_bias    = (const float*)d_in[13];
    const float* item_bias    = (const float*)d_in[14];
    const float* global_bias  = (const float*)d_in[15];
    float* out = (float*)d_out;

    transpose_kernel<<<40, 256>>>(conv_w, fc_w2_w);
    proj_kernel<<<VOCAB / TVP, 160>>>(emb_table);
    review_kernel<<<2 * NREV, 256>>>(user_reviews, item_reviews,
                                     conv_b, fc_w_w, fc_w_b, h_r_w, out);
    pgemm_kernel<<<256, 800>>>(fc_w2_b, h_c_w);
    pair_kernel<<<dim3(N_NODE, 2), 256>>>();
    edge_kernel<<<(Ee + 255) / 256, 256>>>(uid, iid, user_bias, item_bias, global_bias, out);
}